// round 15
// baseline (speedup 1.0000x reference)
#include <cuda_runtime.h>
#include <math_constants.h>

// Problem constants
#define LQ   15876          // L = 126*126 patches
#define HO   126
#define D    27
#define DP   28             // padded dim; K pad = 1.0 (ssum trick), Q pad = 0
#define SPLIT 9             // split-K over keys (15876 = 9 * 1764)
#define BQ   128            // threads per CTA (1 query per thread, 4 warps)
#define BK   252            // key tile in smem (1764 = 7 * 252, no tail)
#define NQB  128            // 16x8 CTA tiles of 8x16 queries (covers 126x126)
#define CH   (LQ / SPLIT)   // 1764 keys per chunk
#define DP2  (DP / 2)       // 14 packed f32x2 values
#define SKIP_THR 18.0f      // log2 skip; measured dropped mass ~1e-9 at 22

typedef unsigned long long u64;

// Scratch (no allocations allowed -> device globals)
__device__ __align__(16) float g_K[LQ * DP];          // x patches (keys/vals)
__device__ __align__(16) float g_Q[LQ * DP];          // y patches (queries)
__device__ float g_yyc[LQ];                            // ||X_m||^2 * log2e/0.35
__device__ float g_pm[SPLIT * LQ];                     // partial max (log2 dom)
__device__ __align__(16) float g_pacc[SPLIT * LQ * DP]; // [..27] holds ssum
__device__ __align__(16) float g_outP[LQ * DP];        // attention out patches

__device__ __forceinline__ float ex2(float x) {
    float r;
    asm("ex2.approx.ftz.f32 %0, %1;" : "=f"(r) : "f"(x));
    return r;
}
__device__ __forceinline__ u64 pack2(float a, float b) {
    u64 r;
    asm("mov.b64 %0, {%1, %2};" : "=l"(r) : "f"(a), "f"(b));
    return r;
}
__device__ __forceinline__ void unpack2(u64 v, float& a, float& b) {
    asm("mov.b64 {%0, %1}, %2;" : "=f"(a), "=f"(b) : "l"(v));
}
// d = a*b + c  (packed 2x fp32)
__device__ __forceinline__ u64 fma2v(u64 a, u64 b, u64 c) {
    u64 d;
    asm("fma.rn.f32x2 %0, %1, %2, %3;" : "=l"(d) : "l"(a), "l"(b), "l"(c));
    return d;
}
__device__ __forceinline__ u64 add2v(u64 a, u64 b) {
    u64 d;
    asm("add.rn.f32x2 %0, %1, %2;" : "=l"(d) : "l"(a), "l"(b));
    return d;
}
__device__ __forceinline__ u64 mul2v(u64 a, u64 b) {
    u64 d;
    asm("mul.rn.f32x2 %0, %1, %2;" : "=l"(d) : "l"(a), "l"(b));
    return d;
}
// load two adjacent u64 (16B) from shared
__device__ __forceinline__ void lds_v2u64(u64& a, u64& b, const void* p) {
    asm("ld.shared.v2.b64 {%0, %1}, [%2];"
        : "=l"(a), "=l"(b) : "l"((size_t)__cvta_generic_to_shared(p)));
}

// ---------------------------------------------------------------------------
// Kernel A: patch extraction + key squared norms. K pad=1.0, Q pad=0.0
// ---------------------------------------------------------------------------
__global__ void extract_kernel(const float* __restrict__ x,
                               const float* __restrict__ y) {
    int m = blockIdx.x * blockDim.x + threadIdx.x;
    if (m >= LQ) return;
    int ph = m / HO, pw = m % HO;
    const float YSC = 1.4426950408889634f / 0.35f;   // log2e / (h^2 + 0.1)
    float yy = 0.f;
#pragma unroll
    for (int c = 0; c < 3; c++)
#pragma unroll
        for (int ki = 0; ki < 3; ki++)
#pragma unroll
            for (int kj = 0; kj < 3; kj++) {
                int j = c * 9 + ki * 3 + kj;
                float vx = x[c * 16384 + (ph + ki) * 128 + (pw + kj)];
                float vy = y[c * 16384 + (ph + ki) * 128 + (pw + kj)];
                g_K[m * DP + j] = vx;
                g_Q[m * DP + j] = vy;
                yy = fmaf(vx, vx, yy);
            }
    g_K[m * DP + 27] = 1.0f;     // ssum-in-accumulator trick
    g_Q[m * DP + 27] = 0.0f;     // keeps dot product exact
    g_yyc[m] = yy * YSC;
}

// ---------------------------------------------------------------------------
// Kernel B: flash attention, split-K, packed f32x2 math, threshold skip.
// R12 inner loop (per-key vote) unchanged; occupancy raised to 5 CTAs/SM
// (BQ=128, 20 warps/SM) for latency hiding. Warp = 4x8 query block.
// score (log2 domain): sc = dot * (2*log2e/0.35) - yyc[m]
// acc[27] accumulates the softmax mass (K pad element = 1).
// ---------------------------------------------------------------------------
__global__ __launch_bounds__(BQ, 5) void attn_kernel() {
    __shared__ __align__(16) float sK[BK * DP];
    __shared__ float sY[BK];

    int tid = threadIdx.x;
    int w = tid >> 5;                       // warp 0..3
    int lane = tid & 31;
    // CTA tile: 8x16 queries at (bh*8, bw*16); warp subtile 4x8 (2x2 warps)
    int bh = blockIdx.x >> 3, bw = blockIdx.x & 7;   // bh 0..15, bw 0..7
    int qrow = min(bh * 8 + (w >> 1) * 4 + (lane >> 3), HO - 1);
    int qcol = min(bw * 16 + (w & 1) * 8 + (lane & 7), HO - 1);
    int ql = qrow * HO + qcol;

    int k0 = blockIdx.y * CH;

    const float S2 = 2.0f * 1.4426950408889634f / 0.35f;

    u64 qv[DP2];
#pragma unroll
    for (int p = 0; p < DP2 / 2; p++) {
        ulonglong2 t = ((const ulonglong2*)&g_Q[ql * DP])[p];
        qv[2 * p] = t.x; qv[2 * p + 1] = t.y;
    }
    u64 acc[DP2];
#pragma unroll
    for (int j = 0; j < DP2; j++) acc[j] = 0ull;
    float mmax = -CUDART_INF_F;

#pragma unroll 1
    for (int tile = 0; tile < CH / BK; tile++) {
        int kt = k0 + tile * BK;
        for (int t = tid; t < BK * (DP / 4); t += BQ) {
            ((float4*)sK)[t] = ((const float4*)g_K)[kt * (DP / 4) + t];
        }
        for (int t = tid; t < BK; t += BQ) sY[t] = g_yyc[kt + t];
        __syncthreads();

        for (int kk = 0; kk < BK; kk++) {
            const char* krow = (const char*)&sK[kk * DP];
            u64 kv[DP2];
#pragma unroll
            for (int p = 0; p < DP2 / 2; p++)
                lds_v2u64(kv[2 * p], kv[2 * p + 1], krow + 16 * p);

            // packed dot product, 2 chains
            u64 d0 = fma2v(qv[0], kv[0], 0ull);
            u64 d1 = fma2v(qv[1], kv[1], 0ull);
#pragma unroll
            for (int j = 2; j < DP2; j += 2) {
                d0 = fma2v(qv[j], kv[j], d0);
                d1 = fma2v(qv[j + 1], kv[j + 1], d1);
            }
            d0 = add2v(d0, d1);
            float lo, hi;
            unpack2(d0, lo, hi);
            float sc = fmaf(lo + hi, S2, -sY[kk]);

            // warp-uniform skip: negligible keys never touch ex2 / acc
            if (__any_sync(0xffffffffu, sc > mmax - SKIP_THR)) {
                if (sc > mmax) {            // rare rescale (peaked softmax)
                    float corr = ex2(mmax - sc);
                    u64 c2 = pack2(corr, corr);
#pragma unroll
                    for (int j = 0; j < DP2; j++) acc[j] = mul2v(acc[j], c2);
                    mmax = sc;
                }
                float p = ex2(sc - mmax);
                u64 p2 = pack2(p, p);
#pragma unroll
                for (int j = 0; j < DP2; j++)
                    acc[j] = fma2v(p2, kv[j], acc[j]);
            }
        }
        __syncthreads();
    }

    {
        int sidx = blockIdx.y * LQ + ql;
        g_pm[sidx] = mmax;
        ulonglong2* dst = (ulonglong2*)&g_pacc[(size_t)sidx * DP];
#pragma unroll
        for (int p = 0; p < DP2 / 2; p++) {
            ulonglong2 t;
            t.x = acc[2 * p]; t.y = acc[2 * p + 1];
            dst[p] = t;
        }
    }
}

// ---------------------------------------------------------------------------
// Kernel C: log-sum-exp merge of the SPLIT partials, normalize.
// o[27] = total softmax mass (from the K-pad trick)
// ---------------------------------------------------------------------------
__global__ void merge_kernel() {
    int q = blockIdx.x * blockDim.x + threadIdx.x;
    if (q >= LQ) return;
    float M = -CUDART_INF_F;
#pragma unroll
    for (int s = 0; s < SPLIT; s++) M = fmaxf(M, g_pm[s * LQ + q]);
    float o[DP];
#pragma unroll
    for (int j = 0; j < DP; j++) o[j] = 0.f;
#pragma unroll
    for (int s = 0; s < SPLIT; s++) {
        float w = ex2(g_pm[s * LQ + q] - M);
        const float4* src = (const float4*)&g_pacc[(size_t)(s * LQ + q) * DP];
#pragma unroll
        for (int p = 0; p < DP / 4; p++) {
            float4 t = src[p];
            o[4 * p]     = fmaf(t.x, w, o[4 * p]);
            o[4 * p + 1] = fmaf(t.y, w, o[4 * p + 1]);
            o[4 * p + 2] = fmaf(t.z, w, o[4 * p + 2]);
            o[4 * p + 3] = fmaf(t.w, w, o[4 * p + 3]);
        }
    }
    float inv = 1.0f / o[27];
#pragma unroll
    for (int p = 0; p < DP / 4; p++) {
        float4 t;
        t.x = o[4 * p] * inv; t.y = o[4 * p + 1] * inv;
        t.z = o[4 * p + 2] * inv; t.w = o[4 * p + 3] * inv;
        ((float4*)&g_outP[q * DP])[p] = t;
    }
}

// ---------------------------------------------------------------------------
// Kernel D: overlap-add fold with analytic contribution counts
// ---------------------------------------------------------------------------
__global__ void fold_kernel(float* __restrict__ out) {
    int idx = blockIdx.x * blockDim.x + threadIdx.x;
    if (idx >= 3 * 128 * 128) return;
    int c = idx / 16384;
    int h = (idx / 128) % 128;
    int w = idx % 128;
    int nh = min(h, 125) - max(0, h - 2) + 1;
    int nw = min(w, 125) - max(0, w - 2) + 1;
    float sum = 0.f;
#pragma unroll
    for (int ki = 0; ki < 3; ki++) {
        int ph = h - ki;
        if (ph < 0 || ph >= HO) continue;
#pragma unroll
        for (int kj = 0; kj < 3; kj++) {
            int pw = w - kj;
            if (pw < 0 || pw >= HO) continue;
            sum += g_outP[(ph * HO + pw) * DP + c * 9 + ki * 3 + kj];
        }
    }
    out[idx] = sum / (float)(nh * nw);
}

// ---------------------------------------------------------------------------
extern "C" void kernel_launch(void* const* d_in, const int* in_sizes, int n_in,
                              void* d_out, int out_size) {
    const float* x = (const float*)d_in[0];
    const float* y = (const float*)d_in[1];
    float* out = (float*)d_out;

    extract_kernel<<<(LQ + 255) / 256, 256>>>(x, y);
    dim3 grid(NQB, SPLIT);
    attn_kernel<<<grid, BQ>>>();
    merge_kernel<<<(LQ + 255) / 256, 256>>>();
    fold_kernel<<<(3 * 128 * 128 + 255) / 256, 256>>>(out);
}

// round 16
// speedup vs baseline: 1.0668x; 1.0668x over previous
#include <cuda_runtime.h>
#include <cuda_fp16.h>
#include <math_constants.h>

// Problem constants
#define LQ   15876          // L = 126*126 patches
#define HO   126
#define D    27
#define DP   28             // padded dim; K pad = 1.0 (ssum trick), Q pad = 0
#define DPH  32             // fp16 key row padded to 32 halves (64B)
#define SPLIT 9             // split-K over keys (15876 = 9 * 1764)
#define BQ   256            // threads per CTA (1 query per thread)
#define BK   252            // key tile in smem (1764 = 7 * 252, no tail)
#define NQB  64             // 8x8 CTA tiles of 16x16 queries (covers 126x126)
#define CH   (LQ / SPLIT)   // 1764 keys per chunk
#define DP2  (DP / 2)       // 14 packed f32x2 values
#define SKIP_THR 18.0f      // log2 skip threshold (exact-path semantics)
#define H_MARGIN 2.0f       // covers fp16 prescreen dot error (>=3 sigma)

typedef unsigned long long u64;

// Scratch (no allocations allowed -> device globals)
__device__ __align__(16) float  g_K[LQ * DP];         // x patches fp32
__device__ __align__(16) __half g_Kh[LQ * DPH];       // x patches fp16 (64B/row)
__device__ __align__(16) float  g_Q[LQ * DP];         // y patches (queries)
__device__ float g_yyc[LQ];                            // ||X_m||^2 * log2e/0.35
__device__ float g_pm[SPLIT * LQ];                     // partial max (log2 dom)
__device__ __align__(16) float g_pacc[SPLIT * LQ * DP]; // [..27] holds ssum
__device__ __align__(16) float g_outP[LQ * DP];        // attention out patches

__device__ __forceinline__ float ex2(float x) {
    float r;
    asm("ex2.approx.ftz.f32 %0, %1;" : "=f"(r) : "f"(x));
    return r;
}
__device__ __forceinline__ u64 pack2(float a, float b) {
    u64 r;
    asm("mov.b64 %0, {%1, %2};" : "=l"(r) : "f"(a), "f"(b));
    return r;
}
__device__ __forceinline__ void unpack2(u64 v, float& a, float& b) {
    asm("mov.b64 {%0, %1}, %2;" : "=f"(a), "=f"(b) : "l"(v));
}
// d = a*b + c  (packed 2x fp32)
__device__ __forceinline__ u64 fma2v(u64 a, u64 b, u64 c) {
    u64 d;
    asm("fma.rn.f32x2 %0, %1, %2, %3;" : "=l"(d) : "l"(a), "l"(b), "l"(c));
    return d;
}
__device__ __forceinline__ u64 add2v(u64 a, u64 b) {
    u64 d;
    asm("add.rn.f32x2 %0, %1, %2;" : "=l"(d) : "l"(a), "l"(b));
    return d;
}
__device__ __forceinline__ u64 mul2v(u64 a, u64 b) {
    u64 d;
    asm("mul.rn.f32x2 %0, %1, %2;" : "=l"(d) : "l"(a), "l"(b));
    return d;
}
// load two adjacent u64 (16B) from shared
__device__ __forceinline__ void lds_v2u64(u64& a, u64& b, const void* p) {
    asm("ld.shared.v2.b64 {%0, %1}, [%2];"
        : "=l"(a), "=l"(b) : "l"((size_t)__cvta_generic_to_shared(p)));
}
__device__ __forceinline__ __half2 u2h(unsigned v) {
    return *reinterpret_cast<__half2*>(&v);
}

// ---------------------------------------------------------------------------
// Kernel A: patch extraction + key squared norms + fp16 key copy.
// K pad = 1.0 (fp32, ssum trick), fp16 row dims 27..31 = 0 (prescreen only).
// ---------------------------------------------------------------------------
__global__ void extract_kernel(const float* __restrict__ x,
                               const float* __restrict__ y) {
    int m = blockIdx.x * blockDim.x + threadIdx.x;
    if (m >= LQ) return;
    int ph = m / HO, pw = m % HO;
    const float YSC = 1.4426950408889634f / 0.35f;   // log2e / (h^2 + 0.1)
    float v[DP];
    float yy = 0.f;
#pragma unroll
    for (int c = 0; c < 3; c++)
#pragma unroll
        for (int ki = 0; ki < 3; ki++)
#pragma unroll
            for (int kj = 0; kj < 3; kj++) {
                int j = c * 9 + ki * 3 + kj;
                float vx = x[c * 16384 + (ph + ki) * 128 + (pw + kj)];
                float vy = y[c * 16384 + (ph + ki) * 128 + (pw + kj)];
                v[j] = vx;
                g_Q[m * DP + j] = vy;
                yy = fmaf(vx, vx, yy);
            }
    v[27] = 1.0f;                 // ssum-in-accumulator trick (fp32 only)
    g_Q[m * DP + 27] = 0.0f;
#pragma unroll
    for (int j = 0; j < DP; j++) g_K[m * DP + j] = v[j];
    __half2* kh = (__half2*)&g_Kh[m * DPH];
#pragma unroll
    for (int p = 0; p < 13; p++)  // dims 0..25
        kh[p] = __floats2half2_rn(v[2 * p], v[2 * p + 1]);
    kh[13] = __floats2half2_rn(v[26], 0.f);   // dim 27 not in prescreen
    kh[14] = __floats2half2_rn(0.f, 0.f);
    kh[15] = __floats2half2_rn(0.f, 0.f);
    g_yyc[m] = yy * YSC;
}

// ---------------------------------------------------------------------------
// Kernel B: flash attention, split-K, fp16 PRESCREEN + exact fp32 update.
// Fast path per key: 4x LDS.128 (h2 row) + 16 HFMA2 + tiny epilogue; the
// vote tests the approximate score against mmax - THR - MARGIN (margin
// covers fp16 dot error, so no key the exact R12 test accepts is missed).
// Flagged keys recompute the exact fp32 dot and run the R12 update.
// acc[27] accumulates the softmax mass (K pad element = 1).
// ---------------------------------------------------------------------------
__global__ __launch_bounds__(BQ, 2) void attn_kernel() {
    __shared__ __align__(16) float sK[BK * DP];          // fp32 rows (exact)
    __shared__ __align__(16) __half sKh[BK * DPH];       // fp16 rows (screen)
    __shared__ float sY[BK];

    int tid = threadIdx.x;
    int w = tid >> 5;                       // warp 0..7
    int lane = tid & 31;
    // CTA tile: 16x16 queries at (bh*16, bw*16); warp subtile 4x8
    int bh = blockIdx.x >> 3, bw = blockIdx.x & 7;
    int qrow = min(bh * 16 + (w >> 1) * 4 + (lane >> 3), HO - 1);
    int qcol = min(bw * 16 + (w & 1) * 8 + (lane & 7), HO - 1);
    int ql = qrow * HO + qcol;

    int k0 = blockIdx.y * CH;

    const float S2 = 2.0f * 1.4426950408889634f / 0.35f;

    u64 qv[DP2];
#pragma unroll
    for (int p = 0; p < DP2 / 2; p++) {
        ulonglong2 t = ((const ulonglong2*)&g_Q[ql * DP])[p];
        qv[2 * p] = t.x; qv[2 * p + 1] = t.y;
    }
    // fp16 query (dims 27..31 zero)
    __half2 qh[16];
#pragma unroll
    for (int p = 0; p < DP2; p++) {
        float a, b;
        unpack2(qv[p], a, b);
        qh[p] = __floats2half2_rn(a, b);
    }
    qh[13] = __floats2half2_rn(__low2float(qh[13]), 0.f); // kill dim 27
    qh[14] = __floats2half2_rn(0.f, 0.f);
    qh[15] = __floats2half2_rn(0.f, 0.f);

    u64 acc[DP2];
#pragma unroll
    for (int j = 0; j < DP2; j++) acc[j] = 0ull;
    float mmax = -CUDART_INF_F;

#pragma unroll 1
    for (int tile = 0; tile < CH / BK; tile++) {
        int kt = k0 + tile * BK;
        for (int t = tid; t < BK * (DP / 4); t += BQ) {
            ((float4*)sK)[t] = ((const float4*)g_K)[kt * (DP / 4) + t];
        }
        for (int t = tid; t < BK * (DPH / 8); t += BQ) {
            ((uint4*)sKh)[t] = ((const uint4*)g_Kh)[kt * (DPH / 8) + t];
        }
        for (int t = tid; t < BK; t += BQ) sY[t] = g_yyc[kt + t];
        __syncthreads();

        for (int kk = 0; kk < BK; kk++) {
            // ---- fp16 prescreen dot: 4 LDS.128 + 16 HFMA2 ----
            const uint4* khrow = (const uint4*)&sKh[kk * DPH];
            uint4 a0 = khrow[0], a1 = khrow[1];
            uint4 a2 = khrow[2], a3 = khrow[3];
            __half2 s0 = __floats2half2_rn(0.f, 0.f), s1 = s0;
            s0 = __hfma2(qh[0],  u2h(a0.x), s0);
            s1 = __hfma2(qh[1],  u2h(a0.y), s1);
            s0 = __hfma2(qh[2],  u2h(a0.z), s0);
            s1 = __hfma2(qh[3],  u2h(a0.w), s1);
            s0 = __hfma2(qh[4],  u2h(a1.x), s0);
            s1 = __hfma2(qh[5],  u2h(a1.y), s1);
            s0 = __hfma2(qh[6],  u2h(a1.z), s0);
            s1 = __hfma2(qh[7],  u2h(a1.w), s1);
            s0 = __hfma2(qh[8],  u2h(a2.x), s0);
            s1 = __hfma2(qh[9],  u2h(a2.y), s1);
            s0 = __hfma2(qh[10], u2h(a2.z), s0);
            s1 = __hfma2(qh[11], u2h(a2.w), s1);
            s0 = __hfma2(qh[12], u2h(a3.x), s0);
            s1 = __hfma2(qh[13], u2h(a3.y), s1);
            s0 = __hadd2(s0, s1);
            float dh = __low2float(s0) + __high2float(s0);
            float sch = fmaf(dh, S2, -sY[kk]);

            // warp-uniform prescreen vote (widened by fp16-error margin)
            if (__any_sync(0xffffffffu,
                           sch > mmax - (SKIP_THR + H_MARGIN))) {
                // ---- exact fp32 dot (R12 path) ----
                const char* krow = (const char*)&sK[kk * DP];
                u64 kv[DP2];
#pragma unroll
                for (int p = 0; p < DP2 / 2; p++)
                    lds_v2u64(kv[2 * p], kv[2 * p + 1], krow + 16 * p);
                u64 d0 = fma2v(qv[0], kv[0], 0ull);
                u64 d1 = fma2v(qv[1], kv[1], 0ull);
#pragma unroll
                for (int j = 2; j < DP2; j += 2) {
                    d0 = fma2v(qv[j], kv[j], d0);
                    d1 = fma2v(qv[j + 1], kv[j + 1], d1);
                }
                d0 = add2v(d0, d1);
                float lo, hi;
                unpack2(d0, lo, hi);
                float sc = fmaf(lo + hi, S2, -sY[kk]);

                if (sc > mmax) {            // rare rescale (peaked softmax)
                    float corr = ex2(mmax - sc);
                    u64 c2 = pack2(corr, corr);
#pragma unroll
                    for (int j = 0; j < DP2; j++) acc[j] = mul2v(acc[j], c2);
                    mmax = sc;
                }
                float p = ex2(sc - mmax);
                u64 p2 = pack2(p, p);
#pragma unroll
                for (int j = 0; j < DP2; j++)
                    acc[j] = fma2v(p2, kv[j], acc[j]);
            }
        }
        __syncthreads();
    }

    {
        int sidx = blockIdx.y * LQ + ql;
        g_pm[sidx] = mmax;
        ulonglong2* dst = (ulonglong2*)&g_pacc[(size_t)sidx * DP];
#pragma unroll
        for (int p = 0; p < DP2 / 2; p++) {
            ulonglong2 t;
            t.x = acc[2 * p]; t.y = acc[2 * p + 1];
            dst[p] = t;
        }
    }
}

// ---------------------------------------------------------------------------
// Kernel C: log-sum-exp merge of the SPLIT partials, normalize.
// o[27] = total softmax mass (from the K-pad trick)
// ---------------------------------------------------------------------------
__global__ void merge_kernel() {
    int q = blockIdx.x * blockDim.x + threadIdx.x;
    if (q >= LQ) return;
    float M = -CUDART_INF_F;
#pragma unroll
    for (int s = 0; s < SPLIT; s++) M = fmaxf(M, g_pm[s * LQ + q]);
    float o[DP];
#pragma unroll
    for (int j = 0; j < DP; j++) o[j] = 0.f;
#pragma unroll
    for (int s = 0; s < SPLIT; s++) {
        float w = ex2(g_pm[s * LQ + q] - M);
        const float4* src = (const float4*)&g_pacc[(size_t)(s * LQ + q) * DP];
#pragma unroll
        for (int p = 0; p < DP / 4; p++) {
            float4 t = src[p];
            o[4 * p]     = fmaf(t.x, w, o[4 * p]);
            o[4 * p + 1] = fmaf(t.y, w, o[4 * p + 1]);
            o[4 * p + 2] = fmaf(t.z, w, o[4 * p + 2]);
            o[4 * p + 3] = fmaf(t.w, w, o[4 * p + 3]);
        }
    }
    float inv = 1.0f / o[27];
#pragma unroll
    for (int p = 0; p < DP / 4; p++) {
        float4 t;
        t.x = o[4 * p] * inv; t.y = o[4 * p + 1] * inv;
        t.z = o[4 * p + 2] * inv; t.w = o[4 * p + 3] * inv;
        ((float4*)&g_outP[q * DP])[p] = t;
    }
}

// ---------------------------------------------------------------------------
// Kernel D: overlap-add fold with analytic contribution counts
// ---------------------------------------------------------------------------
__global__ void fold_kernel(float* __restrict__ out) {
    int idx = blockIdx.x * blockDim.x + threadIdx.x;
    if (idx >= 3 * 128 * 128) return;
    int c = idx / 16384;
    int h = (idx / 128) % 128;
    int w = idx % 128;
    int nh = min(h, 125) - max(0, h - 2) + 1;
    int nw = min(w, 125) - max(0, w - 2) + 1;
    float sum = 0.f;
#pragma unroll
    for (int ki = 0; ki < 3; ki++) {
        int ph = h - ki;
        if (ph < 0 || ph >= HO) continue;
#pragma unroll
        for (int kj = 0; kj < 3; kj++) {
            int pw = w - kj;
            if (pw < 0 || pw >= HO) continue;
            sum += g_outP[(ph * HO + pw) * DP + c * 9 + ki * 3 + kj];
        }
    }
    out[idx] = sum / (float)(nh * nw);
}

// ---------------------------------------------------------------------------
extern "C" void kernel_launch(void* const* d_in, const int* in_sizes, int n_in,
                              void* d_out, int out_size) {
    const float* x = (const float*)d_in[0];
    const float* y = (const float*)d_in[1];
    float* out = (float*)d_out;

    extract_kernel<<<(LQ + 255) / 256, 256>>>(x, y);
    dim3 grid(NQB, SPLIT);
    attn_kernel<<<grid, BQ>>>();
    merge_kernel<<<(LQ + 255) / 256, 256>>>();
    fold_kernel<<<(3 * 128 * 128 + 255) / 256, 256>>>(out);
}